// round 10
// baseline (speedup 1.0000x reference)
#include <cuda_runtime.h>

typedef unsigned long long ull;

#define TT       30
#define BB       1048576
#define THREADS  256

// W2/b2 in constant (LDC port, 6 loads/warp-t); W1/b1 in shared (LDS port).
__constant__ __align__(16) float cW2[TT * 20];      // 600 floats
__constant__ __align__(16) float cB2[TT];           // 30

// ---------------- packed f32x2 helpers ----------------
__device__ __forceinline__ ull pk(float lo, float hi) {
    ull r; asm("mov.b64 %0, {%1,%2};" : "=l"(r) : "f"(lo), "f"(hi)); return r;
}
__device__ __forceinline__ void upk(float& lo, float& hi, ull v) {
    asm("mov.b64 {%0,%1}, %2;" : "=f"(lo), "=f"(hi) : "l"(v));
}
__device__ __forceinline__ ull fma2(ull a, ull b, ull c) {
    ull d; asm("fma.rn.f32x2 %0, %1, %2, %3;" : "=l"(d) : "l"(a), "l"(b), "l"(c)); return d;
}
__device__ __forceinline__ ull add2(ull a, ull b) {
    ull d; asm("add.rn.f32x2 %0, %1, %2;" : "=l"(d) : "l"(a), "l"(b)); return d;
}
__device__ __forceinline__ ull relu2(ull v) {
    float a, b; upk(a, b, v);
    return pk(fmaxf(a, 0.0f), fmaxf(b, 0.0f));
}
// tanh(z) = 1 - 2/(exp(2z)+1) via MUFU.EX2 + MUFU.RCP (~1e-6 rel err)
__device__ __forceinline__ float fast_tanh(float z) {
    float e; asm("ex2.approx.f32 %0, %1;" : "=f"(e) : "f"(z * 2.8853900817779268f));
    float r; asm("rcp.approx.f32 %0, %1;" : "=f"(r) : "f"(e + 1.0f));
    return fmaf(-2.0f, r, 1.0f);
}

// Shared layout (floats):
//   sW1 : [0, 1200)       W1 [T][2][20]
//   sB1 : [1200, 1800)    b1 [T][20]
//   sIO : [1800, 9480)    x/out staging: 256 elems x 30 floats
#define SMEM_FLOATS (1800 + THREADS * TT)   // 9480 floats = 37920 bytes -> 5 CTAs/SM

__global__ __launch_bounds__(THREADS, 5)
void rnn_kernel(const float* __restrict__ gx,
                const float* __restrict__ gW1,
                const float* __restrict__ gb1,
                float* __restrict__ gout)
{
    __shared__ float smem[SMEM_FLOATS];
    float* sW1 = smem;
    float* sB1 = smem + 1200;
    float* sIO = smem + 1800;

    const int tid  = threadIdx.x;
    const int base = blockIdx.x * THREADS;   // element base for this CTA

    // ---- stage W1 + b1 (coalesced float4) ----
    {
        float4*       d = (float4*)sW1;
        const float4* s = (const float4*)gW1;
        for (int i = tid; i < 300; i += THREADS) d[i] = s[i];
        d = (float4*)sB1; s = (const float4*)gb1;
        if (tid < 150) d[tid] = s[tid];
    }
    // ---- stage x (coalesced float4: 256*30 floats = 1920 float4) ----
    {
        float4*       d = (float4*)sIO;
        const float4* s = (const float4*)(gx + (size_t)base * TT);
        for (int i = tid; i < 1920; i += THREADS) d[i] = s[i];
    }
    __syncthreads();

    float* io = sIO + tid * TT;             // this thread's element

    const ull* w1u = (const ull*)sW1;       // per t: 20 ulls (10 row0, 10 row1)
    const ull* b1u = (const ull*)sB1;       // per t: 10 ulls
    const ull* w2u = (const ull*)cW2;       // per t: 10 ulls (constant)

    float o = 0.0f;

    #pragma unroll 1
    for (int t = 0; t < TT; ++t) {
        const ulonglong2* w1t = (const ulonglong2*)(w1u + t * 20);  // LDS.128
        const ulonglong2* b1t = (const ulonglong2*)(b1u + t * 10);  // LDS.128
        const ulonglong2* w2t = (const ulonglong2*)(w2u + t * 10);  // LDC.128
        const float bt2 = cB2[t];
        const float x   = io[t];

        ull xx   = pk(x, x);
        ull oo   = pk(o, o);
        ull accA = pk(bt2, 0.0f);
        ull accB = pk(0.0f, 0.0f);

        #pragma unroll
        for (int q = 0; q < 5; ++q) {
            ulonglong2 wa = w1t[q];       // W1 row0, hidden 4q..4q+3
            ulonglong2 wb = w1t[5 + q];   // W1 row1
            ulonglong2 bb = b1t[q];       // b1
            ulonglong2 w2 = w2t[q];       // W2

            ull hA = fma2(xx, wa.x, fma2(oo, wb.x, bb.x));
            ull hB = fma2(xx, wa.y, fma2(oo, wb.y, bb.y));
            accA = fma2(relu2(hA), w2.x, accA);
            accB = fma2(relu2(hB), w2.y, accB);
        }
        {
            float a, b;
            upk(a, b, add2(accA, accB));
            o = fast_tanh(a + b);
        }
        io[t] = o;      // overwrite consumed x slot with output
    }

    __syncthreads();

    // ---- writeback (coalesced float4) ----
    {
        const float4* s = (const float4*)sIO;
        float4*       d = (float4*)(gout + (size_t)base * TT);
        for (int i = tid; i < 1920; i += THREADS) d[i] = s[i];
    }
}

extern "C" void kernel_launch(void* const* d_in, const int* in_sizes, int n_in,
                              void* d_out, int out_size)
{
    const float* x  = (const float*)d_in[0];
    const float* W1 = (const float*)d_in[1];
    const float* b1 = (const float*)d_in[2];

    // Populate constant bank (graph-capturable D2D memcpys, no allocation).
    void *pW2, *pB2;
    cudaGetSymbolAddress(&pW2, cW2);
    cudaGetSymbolAddress(&pB2, cB2);
    cudaMemcpyAsync(pW2, d_in[3], sizeof(float) * TT * 20, cudaMemcpyDeviceToDevice);
    cudaMemcpyAsync(pB2, d_in[4], sizeof(float) * TT,      cudaMemcpyDeviceToDevice);

    rnn_kernel<<<BB / THREADS, THREADS>>>(x, W1, b1, (float*)d_out);
}

// round 12
// speedup vs baseline: 1.2167x; 1.2167x over previous
#include <cuda_runtime.h>

typedef unsigned long long ull;

#define TT       30
#define BB       1048576
#define THREADS  128
#define M        4
#define QUARTER  (BB / 4)

// Small weights in constant (LDC port); W1 in shared (LDS port).
__constant__ __align__(16) float cB1[TT * 20];      // 600 floats
__constant__ __align__(16) float cW2[TT * 20];      // 600
__constant__ __align__(16) float cB2[TT];           // 30

// ---------------- packed f32x2 helpers ----------------
__device__ __forceinline__ ull pk(float lo, float hi) {
    ull r; asm("mov.b64 %0, {%1,%2};" : "=l"(r) : "f"(lo), "f"(hi)); return r;
}
__device__ __forceinline__ void upk(float& lo, float& hi, ull v) {
    asm("mov.b64 {%0,%1}, %2;" : "=f"(lo), "=f"(hi) : "l"(v));
}
__device__ __forceinline__ ull fma2(ull a, ull b, ull c) {
    ull d; asm("fma.rn.f32x2 %0, %1, %2, %3;" : "=l"(d) : "l"(a), "l"(b), "l"(c)); return d;
}
__device__ __forceinline__ ull add2(ull a, ull b) {
    ull d; asm("add.rn.f32x2 %0, %1, %2;" : "=l"(d) : "l"(a), "l"(b)); return d;
}
__device__ __forceinline__ ull relu2(ull v) {
    float a, b; upk(a, b, v);
    return pk(fmaxf(a, 0.0f), fmaxf(b, 0.0f));
}
// tanh(z) = 1 - 2/(exp(2z)+1) via MUFU.EX2 + MUFU.RCP (~1e-6 rel err)
__device__ __forceinline__ float fast_tanh(float z) {
    float e; asm("ex2.approx.f32 %0, %1;" : "=f"(e) : "f"(z * 2.8853900817779268f));
    float r; asm("rcp.approx.f32 %0, %1;" : "=f"(r) : "f"(e + 1.0f));
    return fmaf(-2.0f, r, 1.0f);
}

#define REGF        (THREADS * TT)      // 3840 floats per region
#define SMEM_IO     (M * REGF)          // 15360 floats = 61440 bytes (dynamic)

__global__ __launch_bounds__(THREADS, 3)
void rnn_kernel(const float* __restrict__ gx,
                const float* __restrict__ gW1,
                float* __restrict__ gout)
{
    // DISTINCT shared objects: weight loads from sW1 can be reordered across
    // io stores into sIO by alias analysis (single-object versions could not).
    __shared__ __align__(16) float sW1[1200];
    extern __shared__ float sIO[];

    const int tid   = threadIdx.x;
    const int ebase = blockIdx.x * THREADS;   // region-0 element base

    // ---- stage W1 (coalesced float4, 300 float4s) ----
    {
        float4*       d = (float4*)sW1;
        const float4* s = (const float4*)gW1;
        for (int i = tid; i < 300; i += THREADS) d[i] = s[i];
    }
    // ---- stage x: M regions, each 960 float4, coalesced ----
    {
        float4* d = (float4*)sIO;
        #pragma unroll
        for (int r = 0; r < M; ++r) {
            const float4* s = (const float4*)(gx + (size_t)(ebase + r * QUARTER) * TT);
            for (int i = tid; i < REGF / 4; i += THREADS) d[r * (REGF / 4) + i] = s[i];
        }
    }
    __syncthreads();

    // This thread's 4 elements
    float* io[M];
    #pragma unroll
    for (int r = 0; r < M; ++r) io[r] = sIO + r * REGF + tid * TT;

    const ulonglong2* w1p = (const ulonglong2*)sW1;   // 10 ulonglong2 per t
    const ull*        b1u = (const ull*)cB1;          // per t: 10 ulls (LDC)
    const ull*        w2u = (const ull*)cW2;          // per t: 10 ulls (LDC)

    float o[M];
    #pragma unroll
    for (int m = 0; m < M; ++m) o[m] = 0.0f;

    #pragma unroll 1
    for (int tt = 0; tt < TT; tt += 2) {
        // ---- phase 1: issue ALL W1 + x loads for both timesteps up-front ----
        ulonglong2 w1v[2][10];
        float      xv[2][M];
        #pragma unroll
        for (int u = 0; u < 2; ++u) {
            const ulonglong2* wp = w1p + (tt + u) * 10;
            #pragma unroll
            for (int q = 0; q < 10; ++q) w1v[u][q] = wp[q];
            #pragma unroll
            for (int m = 0; m < M; ++m)  xv[u][m] = io[m][tt + u];
        }

        // ---- phase 2: compute both timesteps (b1/W2 via LDC: const space
        //      provably non-aliasing with the shared io stores) ----
        #pragma unroll
        for (int u = 0; u < 2; ++u) {
            const int t = tt + u;
            const ulonglong2* b1t = (const ulonglong2*)(b1u + t * 10);  // LDC.128
            const ulonglong2* w2t = (const ulonglong2*)(w2u + t * 10);  // LDC.128
            const float bt2 = cB2[t];

            ull xx[M], oo[M], accA[M], accB[M];
            #pragma unroll
            for (int m = 0; m < M; ++m) {
                xx[m]   = pk(xv[u][m], xv[u][m]);
                oo[m]   = pk(o[m], o[m]);
                accA[m] = pk(bt2, 0.0f);
                accB[m] = pk(0.0f, 0.0f);
            }

            #pragma unroll
            for (int q = 0; q < 5; ++q) {
                ulonglong2 wa = w1v[u][q];       // W1 row0, hidden 4q..4q+3
                ulonglong2 wb = w1v[u][5 + q];   // W1 row1
                ulonglong2 bb = b1t[q];          // b1
                ulonglong2 w2 = w2t[q];          // W2

                #pragma unroll
                for (int m = 0; m < M; ++m) {
                    ull hA = fma2(xx[m], wa.x, fma2(oo[m], wb.x, bb.x));
                    ull hB = fma2(xx[m], wa.y, fma2(oo[m], wb.y, bb.y));
                    accA[m] = fma2(relu2(hA), w2.x, accA[m]);
                    accB[m] = fma2(relu2(hB), w2.y, accB[m]);
                }
            }

            #pragma unroll
            for (int m = 0; m < M; ++m) {
                float a, b;
                upk(a, b, add2(accA[m], accB[m]));
                o[m] = fast_tanh(a + b);
                io[m][t] = o[m];            // output overwrites consumed x slot
            }
        }
    }

    __syncthreads();

    // ---- writeback (coalesced float4) ----
    {
        const float4* s = (const float4*)sIO;
        #pragma unroll
        for (int r = 0; r < M; ++r) {
            float4* d = (float4*)(gout + (size_t)(ebase + r * QUARTER) * TT);
            for (int i = tid; i < REGF / 4; i += THREADS) d[i] = s[r * (REGF / 4) + i];
        }
    }
}

extern "C" void kernel_launch(void* const* d_in, const int* in_sizes, int n_in,
                              void* d_out, int out_size)
{
    const float* x  = (const float*)d_in[0];
    const float* W1 = (const float*)d_in[1];

    // Populate constant bank (graph-capturable D2D memcpys, no allocation).
    void *pB1, *pW2, *pB2;
    cudaGetSymbolAddress(&pB1, cB1);
    cudaGetSymbolAddress(&pW2, cW2);
    cudaGetSymbolAddress(&pB2, cB2);
    cudaMemcpyAsync(pB1, d_in[2], sizeof(float) * TT * 20, cudaMemcpyDeviceToDevice);
    cudaMemcpyAsync(pW2, d_in[3], sizeof(float) * TT * 20, cudaMemcpyDeviceToDevice);
    cudaMemcpyAsync(pB2, d_in[4], sizeof(float) * TT,      cudaMemcpyDeviceToDevice);

    const int smem_bytes = SMEM_IO * (int)sizeof(float);   // 61440
    cudaFuncSetAttribute(rnn_kernel, cudaFuncAttributeMaxDynamicSharedMemorySize, smem_bytes);

    rnn_kernel<<<BB / (M * THREADS), THREADS, smem_bytes>>>(x, W1, (float*)d_out);
}

// round 13
// speedup vs baseline: 1.3380x; 1.0997x over previous
#include <cuda_runtime.h>

typedef unsigned long long ull;

#define TT       30
#define BB       1048576
#define THREADS  64
#define M        4
#define QUARTER  (BB / 4)

// ALL weights in constant memory: LDC port only (33% busy at M=4's 13.8
// warp-streams/SMSP), zero L1tex weight traffic, zero aliasing with io stores.
__constant__ __align__(16) float cW1[TT * 2 * 20];  // 1200 floats
__constant__ __align__(16) float cB1[TT * 20];      // 600
__constant__ __align__(16) float cW2[TT * 20];      // 600
__constant__ __align__(16) float cB2[TT];           // 30

// ---------------- packed f32x2 helpers ----------------
__device__ __forceinline__ ull pk(float lo, float hi) {
    ull r; asm("mov.b64 %0, {%1,%2};" : "=l"(r) : "f"(lo), "f"(hi)); return r;
}
__device__ __forceinline__ void upk(float& lo, float& hi, ull v) {
    asm("mov.b64 {%0,%1}, %2;" : "=f"(lo), "=f"(hi) : "l"(v));
}
__device__ __forceinline__ ull fma2(ull a, ull b, ull c) {
    ull d; asm("fma.rn.f32x2 %0, %1, %2, %3;" : "=l"(d) : "l"(a), "l"(b), "l"(c)); return d;
}
__device__ __forceinline__ ull add2(ull a, ull b) {
    ull d; asm("add.rn.f32x2 %0, %1, %2;" : "=l"(d) : "l"(a), "l"(b)); return d;
}
__device__ __forceinline__ ull relu2(ull v) {
    float a, b; upk(a, b, v);
    return pk(fmaxf(a, 0.0f), fmaxf(b, 0.0f));
}
// tanh(z) = 1 - 2/(exp(2z)+1) via MUFU.EX2 + MUFU.RCP (~1e-6 rel err)
__device__ __forceinline__ float fast_tanh(float z) {
    float e; asm("ex2.approx.f32 %0, %1;" : "=f"(e) : "f"(z * 2.8853900817779268f));
    float r; asm("rcp.approx.f32 %0, %1;" : "=f"(r) : "f"(e + 1.0f));
    return fmaf(-2.0f, r, 1.0f);
}

#define REGF        (THREADS * TT)      // 1920 floats per region
#define SMEM_IO     (M * REGF)          // 7680 floats = 30720 bytes (dynamic)

__global__ __launch_bounds__(THREADS, 7)
void rnn_kernel(const float* __restrict__ gx,
                float* __restrict__ gout)
{
    extern __shared__ float sIO[];

    const int tid   = threadIdx.x;
    const int ebase = blockIdx.x * THREADS;   // region-0 element base

    // ---- stage x: M regions, each 480 float4, coalesced ----
    {
        float4* d = (float4*)sIO;
        #pragma unroll
        for (int r = 0; r < M; ++r) {
            const float4* s = (const float4*)(gx + (size_t)(ebase + r * QUARTER) * TT);
            for (int i = tid; i < REGF / 4; i += THREADS) d[r * (REGF / 4) + i] = s[i];
        }
    }
    __syncthreads();

    // This thread's 4 elements
    float* io[M];
    #pragma unroll
    for (int r = 0; r < M; ++r) io[r] = sIO + r * REGF + tid * TT;

    const ull* w1u = (const ull*)cW1;   // per t: 20 ulls (10 row0 pairs, 10 row1 pairs)
    const ull* b1u = (const ull*)cB1;   // per t: 10 ulls
    const ull* w2u = (const ull*)cW2;   // per t: 10 ulls

    float o[M];
    #pragma unroll
    for (int m = 0; m < M; ++m) o[m] = 0.0f;

    #pragma unroll 2
    for (int t = 0; t < TT; ++t) {
        const ulonglong2* w1t = (const ulonglong2*)(w1u + t * 20);  // LDC.128
        const ulonglong2* b1t = (const ulonglong2*)(b1u + t * 10);  // LDC.128
        const ulonglong2* w2t = (const ulonglong2*)(w2u + t * 10);  // LDC.128
        const float bt2 = cB2[t];

        ull xx[M], oo[M], accA[M], accB[M];
        #pragma unroll
        for (int m = 0; m < M; ++m) {
            float x = io[m][t];
            xx[m]   = pk(x, x);
            oo[m]   = pk(o[m], o[m]);
            accA[m] = pk(bt2, 0.0f);
            accB[m] = pk(0.0f, 0.0f);
        }

        #pragma unroll
        for (int q = 0; q < 5; ++q) {
            ulonglong2 wa = w1t[q];       // W1 row0, hidden 4q..4q+3
            ulonglong2 wb = w1t[5 + q];   // W1 row1
            ulonglong2 bb = b1t[q];       // b1
            ulonglong2 w2 = w2t[q];       // W2

            #pragma unroll
            for (int m = 0; m < M; ++m) {
                ull hA = fma2(xx[m], wa.x, fma2(oo[m], wb.x, bb.x));
                ull hB = fma2(xx[m], wa.y, fma2(oo[m], wb.y, bb.y));
                accA[m] = fma2(relu2(hA), w2.x, accA[m]);
                accB[m] = fma2(relu2(hB), w2.y, accB[m]);
            }
        }

        #pragma unroll
        for (int m = 0; m < M; ++m) {
            float a, b;
            upk(a, b, add2(accA[m], accB[m]));
            o[m] = fast_tanh(a + b);
            io[m][t] = o[m];            // output overwrites consumed x slot
        }
    }

    __syncthreads();

    // ---- writeback (coalesced float4) ----
    {
        const float4* s = (const float4*)sIO;
        #pragma unroll
        for (int r = 0; r < M; ++r) {
            float4* d = (float4*)(gout + (size_t)(ebase + r * QUARTER) * TT);
            for (int i = tid; i < REGF / 4; i += THREADS) d[i] = s[r * (REGF / 4) + i];
        }
    }
}

extern "C" void kernel_launch(void* const* d_in, const int* in_sizes, int n_in,
                              void* d_out, int out_size)
{
    const float* x = (const float*)d_in[0];

    // Populate constant bank (graph-capturable D2D memcpys, no allocation).
    void *pW1, *pB1, *pW2, *pB2;
    cudaGetSymbolAddress(&pW1, cW1);
    cudaGetSymbolAddress(&pB1, cB1);
    cudaGetSymbolAddress(&pW2, cW2);
    cudaGetSymbolAddress(&pB2, cB2);
    cudaMemcpyAsync(pW1, d_in[1], sizeof(float) * TT * 2 * 20, cudaMemcpyDeviceToDevice);
    cudaMemcpyAsync(pB1, d_in[2], sizeof(float) * TT * 20,     cudaMemcpyDeviceToDevice);
    cudaMemcpyAsync(pW2, d_in[3], sizeof(float) * TT * 20,     cudaMemcpyDeviceToDevice);
    cudaMemcpyAsync(pB2, d_in[4], sizeof(float) * TT,          cudaMemcpyDeviceToDevice);

    const int smem_bytes = SMEM_IO * (int)sizeof(float);   // 30720
    cudaFuncSetAttribute(rnn_kernel, cudaFuncAttributeMaxDynamicSharedMemorySize, smem_bytes);

    rnn_kernel<<<BB / (M * THREADS), THREADS, smem_bytes>>>(x, (float*)d_out);
}